// round 1
// baseline (speedup 1.0000x reference)
#include <cuda_runtime.h>

#define BB 2
#define CC 128
#define NN 4096
#define SCALE 0.08838834764831845f   // 128^-0.5

// Scratch (no allocations allowed)
__device__ float g_H[BB*CC*NN];   // groupnorm output, [b][c][n]
__device__ float g_Q[BB*NN*CC];   // [b][n][c]
__device__ float g_K[BB*NN*CC];
__device__ float g_V[BB*NN*CC];
__device__ float g_A[BB*NN*CC];   // attention output, [b][n][c]

// ---------------------------------------------------------------------------
// Kernel 1: GroupNorm. grid = B*32 blocks, one per (batch, group).
// Each group = 4 channels x 4096 spatial = 16384 elements.
// ---------------------------------------------------------------------------
__global__ __launch_bounds__(256) void gn_kernel(
    const float* __restrict__ x,
    const float* __restrict__ gamma,
    const float* __restrict__ beta) {
  int b = blockIdx.x >> 5;
  int g = blockIdx.x & 31;
  const float4* xp = (const float4*)(x + ((size_t)b*CC + g*4)*NN);
  float s = 0.f, s2 = 0.f;
  for (int i = threadIdx.x; i < 4096; i += 256) {
    float4 v = xp[i];
    s  += v.x + v.y + v.z + v.w;
    s2 += v.x*v.x + v.y*v.y + v.z*v.z + v.w*v.w;
  }
  #pragma unroll
  for (int o = 16; o; o >>= 1) {
    s  += __shfl_xor_sync(0xffffffffu, s, o);
    s2 += __shfl_xor_sync(0xffffffffu, s2, o);
  }
  __shared__ float rs[8], rs2[8];
  __shared__ float s_mean, s_rstd;
  int wid = threadIdx.x >> 5;
  if ((threadIdx.x & 31) == 0) { rs[wid] = s; rs2[wid] = s2; }
  __syncthreads();
  if (threadIdx.x == 0) {
    float S = 0.f, S2 = 0.f;
    #pragma unroll
    for (int i = 0; i < 8; i++) { S += rs[i]; S2 += rs2[i]; }
    float mean = S * (1.f/16384.f);
    float var  = S2 * (1.f/16384.f) - mean*mean;
    s_mean = mean;
    s_rstd = rsqrtf(var + 1e-5f);
  }
  __syncthreads();
  float mean = s_mean, rstd = s_rstd;
  float* hp = g_H + ((size_t)b*CC + g*4)*NN;
  for (int i = threadIdx.x; i < 4096; i += 256) {
    int c = g*4 + (i >> 10);
    float ga = gamma[c] * rstd;
    float be = beta[c] - mean * ga;
    float4 v = xp[i];
    float4 o;
    o.x = v.x*ga + be; o.y = v.y*ga + be; o.z = v.z*ga + be; o.w = v.w*ga + be;
    ((float4*)hp)[i] = o;
  }
}

// ---------------------------------------------------------------------------
// Kernel 2: fused Q/K/V GEMM.  out[n][co] = sum_c w[co][c]*H[c][n] + b[co]
// grid = B * 64 token-tiles (64 tokens each), 256 threads.
// Dynamic shared: Hs[128][64] + Ws[128][128] = 98304 B
// Thread: cgrp = t&15 -> 4 tokens, wgrp = t>>4 -> 8 output channels.
// ---------------------------------------------------------------------------
__global__ __launch_bounds__(256) void qkv_kernel(
    const float* __restrict__ wq, const float* __restrict__ bq,
    const float* __restrict__ wk, const float* __restrict__ bk,
    const float* __restrict__ wv, const float* __restrict__ bv) {
  extern __shared__ float smem[];
  float* Hs = smem;               // [128][64]
  float* Ws = smem + 128*64;      // [128][128]

  int b  = blockIdx.x >> 6;
  int n0 = (blockIdx.x & 63) << 6;
  int t  = threadIdx.x;
  const float* Hg = g_H + (size_t)b*CC*NN;

  for (int i = t; i < 128*16; i += 256) {
    int c = i >> 4, j4 = i & 15;
    *(float4*)&Hs[c*64 + j4*4] = *(const float4*)&Hg[(size_t)c*NN + n0 + j4*4];
  }

  const float* Wp[3] = {wq, wk, wv};
  const float* Bp[3] = {bq, bk, bv};
  float* Op[3] = {g_Q, g_K, g_V};

  int cgrp = t & 15;   // token group
  int wgrp = t >> 4;   // out-channel group

  for (int m = 0; m < 3; m++) {
    __syncthreads();
    const float4* wsrc = (const float4*)Wp[m];
    for (int i = t; i < 128*32; i += 256) ((float4*)Ws)[i] = wsrc[i];
    __syncthreads();

    float acc[8][4];
    #pragma unroll
    for (int r = 0; r < 8; r++)
      { acc[r][0]=0.f; acc[r][1]=0.f; acc[r][2]=0.f; acc[r][3]=0.f; }

    #pragma unroll 4
    for (int ci = 0; ci < 128; ci += 4) {
      float4 h0 = *(float4*)&Hs[(ci+0)*64 + cgrp*4];
      float4 h1 = *(float4*)&Hs[(ci+1)*64 + cgrp*4];
      float4 h2 = *(float4*)&Hs[(ci+2)*64 + cgrp*4];
      float4 h3 = *(float4*)&Hs[(ci+3)*64 + cgrp*4];
      #pragma unroll
      for (int r = 0; r < 8; r++) {
        float4 w = *(float4*)&Ws[(wgrp*8+r)*128 + ci];
        acc[r][0] += w.x*h0.x + w.y*h1.x + w.z*h2.x + w.w*h3.x;
        acc[r][1] += w.x*h0.y + w.y*h1.y + w.z*h2.y + w.w*h3.y;
        acc[r][2] += w.x*h0.z + w.y*h1.z + w.z*h2.z + w.w*h3.z;
        acc[r][3] += w.x*h0.w + w.y*h1.w + w.z*h2.w + w.w*h3.w;
      }
    }
    float bb[8];
    #pragma unroll
    for (int r = 0; r < 8; r++) bb[r] = Bp[m][wgrp*8 + r];

    float* out = Op[m] + (size_t)b*NN*CC;
    #pragma unroll
    for (int j = 0; j < 4; j++) {
      int n = n0 + cgrp*4 + j;
      float4 o0, o1;
      o0.x = acc[0][j]+bb[0]; o0.y = acc[1][j]+bb[1];
      o0.z = acc[2][j]+bb[2]; o0.w = acc[3][j]+bb[3];
      o1.x = acc[4][j]+bb[4]; o1.y = acc[5][j]+bb[5];
      o1.z = acc[6][j]+bb[6]; o1.w = acc[7][j]+bb[7];
      *(float4*)&out[(size_t)n*CC + wgrp*8]     = o0;
      *(float4*)&out[(size_t)n*CC + wgrp*8 + 4] = o1;
    }
  }
}

// ---------------------------------------------------------------------------
// Kernel 3: flash attention. grid = B * 64 query-tiles (64 queries), 256 thr.
// Q,K stored k-major in shared (stride 68) -> conflict-free float4 S-phase.
// Dynamic shared: Qs 128*68 + Ks 128*68 + Vs 64*128 + Ps 64*68 + 192 stats
//                = 120576 B
// ---------------------------------------------------------------------------
__global__ __launch_bounds__(256) void attn_kernel() {
  extern __shared__ float smem[];
  float* Qs   = smem;                // k-major [128][68]
  float* Ks   = Qs + 128*68;         // k-major [128][68]
  float* Vs   = Ks + 128*68;         // row-major [64][128]
  float* Ps   = Vs + 64*128;         // [64][68]
  float* smax = Ps + 64*68;
  float* ssum = smax + 64;
  float* sal  = ssum + 64;

  int b  = blockIdx.x >> 6;
  int q0 = (blockIdx.x & 63) << 6;
  int t  = threadIdx.x;

  const float* Qg = g_Q + ((size_t)b*NN + q0)*CC;
  const float* Kg = g_K + (size_t)b*NN*CC;
  const float* Vg = g_V + (size_t)b*NN*CC;

  // transposed Q load: Qs[c][row]
  for (int i = t; i < 64*128; i += 256) {
    int row = i >> 7, c = i & 127;
    Qs[c*68 + row] = Qg[i];
  }
  if (t < 64) { smax[t] = -3.0e38f; ssum[t] = 0.f; }

  int ty = t & 15, tx = t >> 4;       // S-phase: rows ty*4.., cols tx*4..
  int rgrp = t >> 5, cgrp = t & 31;   // PV: rows rgrp*8.., chans cgrp*4..

  float acc[8][4];
  #pragma unroll
  for (int r = 0; r < 8; r++)
    { acc[r][0]=0.f; acc[r][1]=0.f; acc[r][2]=0.f; acc[r][3]=0.f; }

  for (int kt = 0; kt < 64; kt++) {
    __syncthreads();   // previous PV done before Ks/Vs/Ps overwritten
    const float* Kt = Kg + (size_t)(kt << 6)*CC;
    for (int i = t; i < 64*128; i += 256) {
      int row = i >> 7, c = i & 127;
      Ks[c*68 + row] = Kt[i];
    }
    const float4* Vt = (const float4*)(Vg + (size_t)(kt << 6)*CC);
    for (int i = t; i < 64*32; i += 256) ((float4*)Vs)[i] = Vt[i];
    __syncthreads();

    // ---- S = Q K^T (4x4 per thread) ----
    float s[4][4];
    #pragma unroll
    for (int r=0;r<4;r++){ s[r][0]=0.f; s[r][1]=0.f; s[r][2]=0.f; s[r][3]=0.f; }
    #pragma unroll 4
    for (int k = 0; k < 128; k++) {
      float4 q  = *(float4*)&Qs[k*68 + ty*4];
      float4 kk = *(float4*)&Ks[k*68 + tx*4];
      s[0][0]+=q.x*kk.x; s[0][1]+=q.x*kk.y; s[0][2]+=q.x*kk.z; s[0][3]+=q.x*kk.w;
      s[1][0]+=q.y*kk.x; s[1][1]+=q.y*kk.y; s[1][2]+=q.y*kk.z; s[1][3]+=q.y*kk.w;
      s[2][0]+=q.z*kk.x; s[2][1]+=q.z*kk.y; s[2][2]+=q.z*kk.z; s[2][3]+=q.z*kk.w;
      s[3][0]+=q.w*kk.x; s[3][1]+=q.w*kk.y; s[3][2]+=q.w*kk.z; s[3][3]+=q.w*kk.w;
    }
    #pragma unroll
    for (int r = 0; r < 4; r++) {
      float4 v;
      v.x = s[r][0]*SCALE; v.y = s[r][1]*SCALE;
      v.z = s[r][2]*SCALE; v.w = s[r][3]*SCALE;
      *(float4*)&Ps[(ty*4+r)*68 + tx*4] = v;
    }
    __syncthreads();

    // ---- online softmax: one thread per row ----
    if (t < 64) {
      float* Pr = Ps + t*68;
      float mx = -3.0e38f;
      #pragma unroll
      for (int j = 0; j < 64; j += 4) {
        float4 v = *(float4*)&Pr[j];
        mx = fmaxf(mx, fmaxf(fmaxf(v.x, v.y), fmaxf(v.z, v.w)));
      }
      float mo = smax[t];
      float mn = fmaxf(mo, mx);
      float sum = 0.f;
      #pragma unroll
      for (int j = 0; j < 64; j += 4) {
        float4 v = *(float4*)&Pr[j];
        v.x = __expf(v.x - mn); v.y = __expf(v.y - mn);
        v.z = __expf(v.z - mn); v.w = __expf(v.w - mn);
        *(float4*)&Pr[j] = v;
        sum += v.x + v.y + v.z + v.w;
      }
      float al = __expf(mo - mn);
      ssum[t] = ssum[t]*al + sum;
      smax[t] = mn;
      sal[t]  = al;
    }
    __syncthreads();

    // ---- O = O*alpha + P V ----
    #pragma unroll
    for (int r = 0; r < 8; r++) {
      float a = sal[rgrp*8 + r];
      acc[r][0]*=a; acc[r][1]*=a; acc[r][2]*=a; acc[r][3]*=a;
    }
    #pragma unroll 2
    for (int j = 0; j < 64; j += 4) {
      float4 v0 = *(float4*)&Vs[(j+0)*128 + cgrp*4];
      float4 v1 = *(float4*)&Vs[(j+1)*128 + cgrp*4];
      float4 v2 = *(float4*)&Vs[(j+2)*128 + cgrp*4];
      float4 v3 = *(float4*)&Vs[(j+3)*128 + cgrp*4];
      #pragma unroll
      for (int r = 0; r < 8; r++) {
        float4 p = *(float4*)&Ps[(rgrp*8+r)*68 + j];
        acc[r][0] += p.x*v0.x + p.y*v1.x + p.z*v2.x + p.w*v3.x;
        acc[r][1] += p.x*v0.y + p.y*v1.y + p.z*v2.y + p.w*v3.y;
        acc[r][2] += p.x*v0.z + p.y*v1.z + p.z*v2.z + p.w*v3.z;
        acc[r][3] += p.x*v0.w + p.y*v1.w + p.z*v2.w + p.w*v3.w;
      }
    }
  }
  __syncthreads();

  float* Ag = g_A + ((size_t)b*NN + q0)*CC;
  #pragma unroll
  for (int r = 0; r < 8; r++) {
    int row = rgrp*8 + r;
    float inv = 1.f / ssum[row];
    float4 v;
    v.x = acc[r][0]*inv; v.y = acc[r][1]*inv;
    v.z = acc[r][2]*inv; v.w = acc[r][3]*inv;
    *(float4*)&Ag[(size_t)row*CC + cgrp*4] = v;
  }
}

// ---------------------------------------------------------------------------
// Kernel 4: projection + bias + residual.
// out[b][co][n] = x[b][co][n] + sum_c wp[co][c]*A[b][n][c] + bp[co]
// Dynamic shared: As[64][132] + Ws[128][128] = 99328 B
// ---------------------------------------------------------------------------
__global__ __launch_bounds__(256) void proj_kernel(
    const float* __restrict__ x,
    const float* __restrict__ wp,
    const float* __restrict__ bp,
    float* __restrict__ outp) {
  extern __shared__ float smem[];
  float* As = smem;               // [64][132]
  float* Ws = smem + 64*132;      // [128][128]

  int b  = blockIdx.x >> 6;
  int n0 = (blockIdx.x & 63) << 6;
  int t  = threadIdx.x;
  const float4* Ag = (const float4*)(g_A + ((size_t)b*NN + n0)*CC);

  for (int i = t; i < 64*32; i += 256) {
    int row = i >> 5, c4 = i & 31;
    *(float4*)&As[row*132 + c4*4] = Ag[i];
  }
  const float4* wsrc = (const float4*)wp;
  for (int i = t; i < 128*32; i += 256) ((float4*)Ws)[i] = wsrc[i];
  __syncthreads();

  int cgrp = t & 15;   // 4 tokens
  int wgrp = t >> 4;   // 8 out-channels

  float acc[8][4];
  #pragma unroll
  for (int r = 0; r < 8; r++)
    { acc[r][0]=0.f; acc[r][1]=0.f; acc[r][2]=0.f; acc[r][3]=0.f; }

  #pragma unroll 4
  for (int ci = 0; ci < 128; ci += 4) {
    float4 a0 = *(float4*)&As[(cgrp*4+0)*132 + ci];
    float4 a1 = *(float4*)&As[(cgrp*4+1)*132 + ci];
    float4 a2 = *(float4*)&As[(cgrp*4+2)*132 + ci];
    float4 a3 = *(float4*)&As[(cgrp*4+3)*132 + ci];
    #pragma unroll
    for (int r = 0; r < 8; r++) {
      float4 w = *(float4*)&Ws[(wgrp*8+r)*128 + ci];
      acc[r][0] += w.x*a0.x + w.y*a0.y + w.z*a0.z + w.w*a0.w;
      acc[r][1] += w.x*a1.x + w.y*a1.y + w.z*a1.z + w.w*a1.w;
      acc[r][2] += w.x*a2.x + w.y*a2.y + w.z*a2.z + w.w*a2.w;
      acc[r][3] += w.x*a3.x + w.y*a3.y + w.z*a3.z + w.w*a3.w;
    }
  }

  #pragma unroll
  for (int r = 0; r < 8; r++) {
    int co = wgrp*8 + r;
    float bias = bp[co];
    size_t base = (size_t)b*CC*NN + (size_t)co*NN + n0 + cgrp*4;
    float4 xv = *(const float4*)&x[base];
    float4 o;
    o.x = xv.x + acc[r][0] + bias;
    o.y = xv.y + acc[r][1] + bias;
    o.z = xv.z + acc[r][2] + bias;
    o.w = xv.w + acc[r][3] + bias;
    *(float4*)&outp[base] = o;
  }
}

// ---------------------------------------------------------------------------
extern "C" void kernel_launch(void* const* d_in, const int* in_sizes, int n_in,
                              void* d_out, int out_size) {
  (void)in_sizes; (void)n_in; (void)out_size;
  const float* x    = (const float*)d_in[0];
  const float* gn_w = (const float*)d_in[1];
  const float* gn_b = (const float*)d_in[2];
  const float* wq   = (const float*)d_in[3];
  const float* bq   = (const float*)d_in[4];
  const float* wk   = (const float*)d_in[5];
  const float* bk   = (const float*)d_in[6];
  const float* wv   = (const float*)d_in[7];
  const float* bv   = (const float*)d_in[8];
  const float* wp   = (const float*)d_in[9];
  const float* bp   = (const float*)d_in[10];
  float* out = (float*)d_out;

  const int QKV_SMEM  = (128*64 + 128*128) * 4;              // 98304
  const int ATTN_SMEM = (128*68*2 + 64*128 + 64*68 + 192)*4; // 120576
  const int PROJ_SMEM = (64*132 + 128*128) * 4;              // 99328
  cudaFuncSetAttribute(qkv_kernel,  cudaFuncAttributeMaxDynamicSharedMemorySize, QKV_SMEM);
  cudaFuncSetAttribute(attn_kernel, cudaFuncAttributeMaxDynamicSharedMemorySize, ATTN_SMEM);
  cudaFuncSetAttribute(proj_kernel, cudaFuncAttributeMaxDynamicSharedMemorySize, PROJ_SMEM);

  gn_kernel<<<64, 256>>>(x, gn_w, gn_b);
  qkv_kernel<<<128, 256, QKV_SMEM>>>(wq, bq, wk, bk, wv, bv);
  attn_kernel<<<128, 256, ATTN_SMEM>>>();
  proj_kernel<<<128, 256, PROJ_SMEM>>>(x, wp, bp, out);
}

// round 6
// speedup vs baseline: 3.8569x; 3.8569x over previous
#include <cuda_runtime.h>
#include <cuda_bf16.h>
#include <stdint.h>

#define BB 2
#define CC 128
#define NN 4096
#define SCALE 0.08838834764831845f   // 128^-0.5

// ---------------- scratch (no allocations allowed) -------------------------
__device__ float          g_H [BB*CC*NN];     // groupnorm out, [b][c][n] fp32
__device__ __nv_bfloat16  g_Qh[BB*NN*CC];     // [b][n][c] bf16
__device__ __nv_bfloat16  g_Kh[BB*NN*CC];     // [b][n][c] bf16
__device__ __nv_bfloat16  g_Vt[BB*CC*NN];     // [b][c][n] bf16 (transposed V)
__device__ float          g_Op[BB*2*NN*CC];   // partial O, [b][sp][n][c]
__device__ float          g_l [BB*2*NN];      // partial softmax sums
__device__ float          g_A [BB*NN*CC];     // combined attn out, [b][n][c]

// single dynamic-shared symbol for all kernels
extern __shared__ char dynsmem[];

// ---------------- PTX helpers (baseline-safe: ldmatrix + mma.sync) ---------
__device__ __forceinline__ uint32_t smem_u32(const void* p) {
  uint32_t a;
  asm("{ .reg .u64 t; cvta.to.shared.u64 t, %1; cvt.u32.u64 %0, t; }"
      : "=r"(a) : "l"(p));
  return a;
}
__device__ __forceinline__ void ldsm_x4(uint32_t& r0, uint32_t& r1,
                                        uint32_t& r2, uint32_t& r3, uint32_t a) {
  asm volatile("ldmatrix.sync.aligned.m8n8.x4.shared.b16 {%0,%1,%2,%3}, [%4];"
               : "=r"(r0), "=r"(r1), "=r"(r2), "=r"(r3) : "r"(a));
}
__device__ __forceinline__ void ldsm_x2(uint32_t& r0, uint32_t& r1, uint32_t a) {
  asm volatile("ldmatrix.sync.aligned.m8n8.x2.shared.b16 {%0,%1}, [%2];"
               : "=r"(r0), "=r"(r1) : "r"(a));
}
__device__ __forceinline__ void mma_bf16(float* d, const uint32_t* a,
                                         const uint32_t* b, const float* c) {
  asm volatile(
    "mma.sync.aligned.m16n8k16.row.col.f32.bf16.bf16.f32 "
    "{%0,%1,%2,%3}, {%4,%5,%6,%7}, {%8,%9}, {%10,%11,%12,%13};"
    : "=f"(d[0]), "=f"(d[1]), "=f"(d[2]), "=f"(d[3])
    : "r"(a[0]), "r"(a[1]), "r"(a[2]), "r"(a[3]),
      "r"(b[0]), "r"(b[1]),
      "f"(c[0]), "f"(c[1]), "f"(c[2]), "f"(c[3]));
}
__device__ __forceinline__ uint32_t pk2(float lo, float hi) {
  uint32_t r;
  asm("cvt.rn.bf16x2.f32 %0, %1, %2;" : "=r"(r) : "f"(hi), "f"(lo));
  return r;
}

// ---------------------------------------------------------------------------
// Kernel 1: GroupNorm
// ---------------------------------------------------------------------------
__global__ __launch_bounds__(256) void gn_kernel(
    const float* __restrict__ x,
    const float* __restrict__ gamma,
    const float* __restrict__ beta) {
  int b = blockIdx.x >> 5;
  int g = blockIdx.x & 31;
  const float4* xp = (const float4*)(x + ((size_t)b*CC + g*4)*NN);
  float s = 0.f, s2 = 0.f;
  for (int i = threadIdx.x; i < 4096; i += 256) {
    float4 v = xp[i];
    s  += v.x + v.y + v.z + v.w;
    s2 += v.x*v.x + v.y*v.y + v.z*v.z + v.w*v.w;
  }
  #pragma unroll
  for (int o = 16; o; o >>= 1) {
    s  += __shfl_xor_sync(0xffffffffu, s, o);
    s2 += __shfl_xor_sync(0xffffffffu, s2, o);
  }
  __shared__ float rs[8], rs2[8];
  __shared__ float s_mean, s_rstd;
  int wid = threadIdx.x >> 5;
  if ((threadIdx.x & 31) == 0) { rs[wid] = s; rs2[wid] = s2; }
  __syncthreads();
  if (threadIdx.x == 0) {
    float S = 0.f, S2 = 0.f;
    #pragma unroll
    for (int i = 0; i < 8; i++) { S += rs[i]; S2 += rs2[i]; }
    float mean = S * (1.f/16384.f);
    float var  = S2 * (1.f/16384.f) - mean*mean;
    s_mean = mean;
    s_rstd = rsqrtf(var + 1e-5f);
  }
  __syncthreads();
  float mean = s_mean, rstd = s_rstd;
  float* hp = g_H + ((size_t)b*CC + g*4)*NN;
  for (int i = threadIdx.x; i < 4096; i += 256) {
    int c = g*4 + (i >> 10);
    float ga = gamma[c] * rstd;
    float be = beta[c] - mean * ga;
    float4 v = xp[i];
    float4 o;
    o.x = v.x*ga + be; o.y = v.y*ga + be; o.z = v.z*ga + be; o.w = v.w*ga + be;
    ((float4*)hp)[i] = o;
  }
}

// ---------------------------------------------------------------------------
// Kernel 2: fused Q/K/V GEMM -> bf16 outputs (Q,K in [n][c]; V^T in [c][n])
// ---------------------------------------------------------------------------
__global__ __launch_bounds__(256) void qkv_kernel(
    const float* __restrict__ wq, const float* __restrict__ bq,
    const float* __restrict__ wk, const float* __restrict__ bk,
    const float* __restrict__ wv, const float* __restrict__ bv) {
  float* smem = (float*)dynsmem;
  float* Hs = smem;               // [128][64]
  float* Ws = smem + 128*64;      // [128][128]

  int b  = blockIdx.x >> 6;
  int n0 = (blockIdx.x & 63) << 6;
  int t  = threadIdx.x;
  const float* Hg = g_H + (size_t)b*CC*NN;

  for (int i = t; i < 128*16; i += 256) {
    int c = i >> 4, j4 = i & 15;
    *(float4*)&Hs[c*64 + j4*4] = *(const float4*)&Hg[(size_t)c*NN + n0 + j4*4];
  }

  const float* Wp[3] = {wq, wk, wv};
  const float* Bp[3] = {bq, bk, bv};

  int cgrp = t & 15;   // token group (4 tokens)
  int wgrp = t >> 4;   // out-channel group (8 channels)

  for (int m = 0; m < 3; m++) {
    __syncthreads();
    const float4* wsrc = (const float4*)Wp[m];
    for (int i = t; i < 128*32; i += 256) ((float4*)Ws)[i] = wsrc[i];
    __syncthreads();

    float acc[8][4];
    #pragma unroll
    for (int r = 0; r < 8; r++)
      { acc[r][0]=0.f; acc[r][1]=0.f; acc[r][2]=0.f; acc[r][3]=0.f; }

    #pragma unroll 4
    for (int ci = 0; ci < 128; ci += 4) {
      float4 h0 = *(float4*)&Hs[(ci+0)*64 + cgrp*4];
      float4 h1 = *(float4*)&Hs[(ci+1)*64 + cgrp*4];
      float4 h2 = *(float4*)&Hs[(ci+2)*64 + cgrp*4];
      float4 h3 = *(float4*)&Hs[(ci+3)*64 + cgrp*4];
      #pragma unroll
      for (int r = 0; r < 8; r++) {
        float4 w = *(float4*)&Ws[(wgrp*8+r)*128 + ci];
        acc[r][0] += w.x*h0.x + w.y*h1.x + w.z*h2.x + w.w*h3.x;
        acc[r][1] += w.x*h0.y + w.y*h1.y + w.z*h2.y + w.w*h3.y;
        acc[r][2] += w.x*h0.z + w.y*h1.z + w.z*h2.z + w.w*h3.z;
        acc[r][3] += w.x*h0.w + w.y*h1.w + w.z*h2.w + w.w*h3.w;
      }
    }
    float bb[8];
    #pragma unroll
    for (int r = 0; r < 8; r++) bb[r] = Bp[m][wgrp*8 + r];

    if (m < 2) {
      __nv_bfloat16* out = (m == 0 ? g_Qh : g_Kh) + (size_t)b*NN*CC;
      #pragma unroll
      for (int j = 0; j < 4; j++) {
        int n = n0 + cgrp*4 + j;
        uint4 o;
        o.x = pk2(acc[0][j]+bb[0], acc[1][j]+bb[1]);
        o.y = pk2(acc[2][j]+bb[2], acc[3][j]+bb[3]);
        o.z = pk2(acc[4][j]+bb[4], acc[5][j]+bb[5]);
        o.w = pk2(acc[6][j]+bb[6], acc[7][j]+bb[7]);
        *(uint4*)(out + (size_t)n*CC + wgrp*8) = o;
      }
    } else {
      __nv_bfloat16* out = g_Vt + (size_t)b*CC*NN;
      #pragma unroll
      for (int r = 0; r < 8; r++) {
        int co = wgrp*8 + r;
        uint2 o;
        o.x = pk2(acc[r][0]+bb[r], acc[r][1]+bb[r]);
        o.y = pk2(acc[r][2]+bb[r], acc[r][3]+bb[r]);
        *(uint2*)(out + (size_t)co*NN + n0 + cgrp*4) = o;
      }
    }
  }
}

// ---------------------------------------------------------------------------
// Kernel 3: bf16 HMMA flash attention (mma.sync m16n8k16), no-max softmax,
// split-KV x2. grid = BB*32 qtiles*2 = 128 CTAs, 256 threads (8 warps).
// Warp w owns q rows [w*16, w*16+16). Per 64-key tile:
//   S = Q K^T  (nb=8 key-blocks x ks=8 k-steps of 16 ch)
//   P = exp(S*scale) in regs; row sums reduced in quad
//   O += P V   (ks=4 key-steps of 16 x nb=16 ch-blocks)
// SMEM: Q stage [128][256B] (32KB) reused as K [64][256B] | V^T [128][128B].
// XOR-16B swizzle: chunk' = chunk ^ (row & 7).
// ---------------------------------------------------------------------------
__global__ __launch_bounds__(256) void attn_kernel() {
  char* smem = dynsmem;
  uint32_t sb = smem_u32(smem);
  const uint32_t Ks = sb;            // 16384 B
  const uint32_t Vs = sb + 16384;    // 16384 B

  int t    = threadIdx.x;
  int w    = t >> 5;
  int lane = t & 31;
  int bid  = blockIdx.x;
  int b    = bid >> 6;
  int qt   = (bid >> 1) & 31;
  int sp   = bid & 1;
  int q0   = qt << 7;
  int kb0  = sp << 11;

  // ---- stage Q tile to smem (swizzled), load A-fragments ----
  for (int i = t; i < 2048; i += 256) {
    int row = i >> 4, cb = i & 15;
    *(uint4*)(smem + row*256 + ((cb ^ (row & 7)) << 4)) =
        *(const uint4*)(g_Qh + ((size_t)b*NN + q0 + row)*CC + cb*8);
  }
  __syncthreads();

  uint32_t qa[8][4];
  {
    int row = w*16 + (lane & 15);
    int kc  = (lane >> 4) & 1;
    #pragma unroll
    for (int ks = 0; ks < 8; ks++) {
      uint32_t a = sb + row*256 + (((2*ks + kc) ^ (row & 7)) << 4);
      ldsm_x4(qa[ks][0], qa[ks][1], qa[ks][2], qa[ks][3], a);
    }
  }
  __syncthreads();   // Q frags in regs; smem free for K/V

  int rl = lane & 7;
  int hf = (lane >> 3) & 1;

  float oacc[16][4];
  #pragma unroll
  for (int nb = 0; nb < 16; nb++)
    { oacc[nb][0]=0.f; oacc[nb][1]=0.f; oacc[nb][2]=0.f; oacc[nb][3]=0.f; }
  float l0 = 0.f, l1 = 0.f;

  for (int kt = 0; kt < 32; kt++) {
    int kb = kb0 + (kt << 6);
    __syncthreads();
    // K tile [64 keys][128 ch]
    for (int i = t; i < 1024; i += 256) {
      int row = i >> 4, cb = i & 15;
      *(uint4*)(smem + row*256 + ((cb ^ (row & 7)) << 4)) =
          *(const uint4*)(g_Kh + ((size_t)b*NN + kb + row)*CC + cb*8);
    }
    // V^T tile [128 ch][64 keys]
    for (int i = t; i < 1024; i += 256) {
      int row = i >> 3, cb = i & 7;
      *(uint4*)(smem + 16384 + row*128 + ((cb ^ (row & 7)) << 4)) =
          *(const uint4*)(g_Vt + ((size_t)b*CC + row)*NN + kb + cb*8);
    }
    __syncthreads();

    // ---- S = Q K^T ----
    float sacc[8][4];
    #pragma unroll
    for (int nb = 0; nb < 8; nb++) {
      sacc[nb][0]=0.f; sacc[nb][1]=0.f; sacc[nb][2]=0.f; sacc[nb][3]=0.f;
      #pragma unroll
      for (int ks = 0; ks < 8; ks++) {
        uint32_t bb[2];
        uint32_t a = Ks + ((nb*8 + rl) << 8) + (((2*ks + hf) ^ rl) << 4);
        ldsm_x2(bb[0], bb[1], a);
        mma_bf16(sacc[nb], qa[ks], bb, sacc[nb]);
      }
    }

    // ---- exp + row sums (regs) ----
    float rs0 = 0.f, rs1 = 0.f;
    #pragma unroll
    for (int nb = 0; nb < 8; nb++) {
      float p0 = __expf(fminf(sacc[nb][0]*SCALE, 80.f));
      float p1 = __expf(fminf(sacc[nb][1]*SCALE, 80.f));
      float p2 = __expf(fminf(sacc[nb][2]*SCALE, 80.f));
      float p3 = __expf(fminf(sacc[nb][3]*SCALE, 80.f));
      sacc[nb][0]=p0; sacc[nb][1]=p1; sacc[nb][2]=p2; sacc[nb][3]=p3;
      rs0 += p0 + p1;
      rs1 += p2 + p3;
    }
    rs0 += __shfl_xor_sync(0xffffffffu, rs0, 1);
    rs0 += __shfl_xor_sync(0xffffffffu, rs0, 2);
    rs1 += __shfl_xor_sync(0xffffffffu, rs1, 1);
    rs1 += __shfl_xor_sync(0xffffffffu, rs1, 2);
    l0 += rs0;
    l1 += rs1;

    // ---- O += P V ----
    #pragma unroll
    for (int ks = 0; ks < 4; ks++) {
      uint32_t pa[4];
      pa[0] = pk2(sacc[2*ks][0],   sacc[2*ks][1]);
      pa[1] = pk2(sacc[2*ks][2],   sacc[2*ks][3]);
      pa[2] = pk2(sacc[2*ks+1][0], sacc[2*ks+1][1]);
      pa[3] = pk2(sacc[2*ks+1][2], sacc[2*ks+1][3]);
      #pragma unroll
      for (int nb = 0; nb < 16; nb++) {
        uint32_t bb[2];
        uint32_t a = Vs + ((nb*8 + rl) << 7) + (((2*ks + hf) ^ rl) << 4);
        ldsm_x2(bb[0], bb[1], a);
        mma_bf16(oacc[nb], pa, bb, oacc[nb]);
      }
    }
  }

  // ---- epilogue: partial O and l ----
  int r0 = q0 + w*16 + (lane >> 2);
  float* Og = g_Op + ((size_t)(b*2 + sp)*NN + r0)*CC;
  int col = (lane & 3)*2;
  #pragma unroll
  for (int nb = 0; nb < 16; nb++) {
    float2 v0 = {oacc[nb][0], oacc[nb][1]};
    float2 v1 = {oacc[nb][2], oacc[nb][3]};
    *(float2*)(Og + nb*8 + col)          = v0;
    *(float2*)(Og + (size_t)8*CC + nb*8 + col) = v1;
  }
  if ((lane & 3) == 0) {
    g_l[(size_t)(b*2 + sp)*NN + r0]     = l0;
    g_l[(size_t)(b*2 + sp)*NN + r0 + 8] = l1;
  }
}

// ---------------------------------------------------------------------------
// Kernel 3b: combine split-KV partials -> g_A [b][n][c] fp32
// ---------------------------------------------------------------------------
__global__ __launch_bounds__(256) void combine_kernel() {
  int gi  = blockIdx.x * 256 + threadIdx.x;   // float4 index over [B][N][C]
  int ngl = gi >> 5;                          // b*NN + n
  int b   = ngl >> 12;
  int n   = ngl & 4095;
  float l = g_l[(size_t)(b*2)*NN + n] + g_l[(size_t)(b*2+1)*NN + n];
  float inv = 1.f / l;
  const float4* O = (const float4*)g_Op;
  float4 a = O[gi + (size_t)b*131072];
  float4 c = O[gi + (size_t)b*131072 + 131072];
  float4 o;
  o.x = (a.x + c.x) * inv; o.y = (a.y + c.y) * inv;
  o.z = (a.z + c.z) * inv; o.w = (a.w + c.w) * inv;
  ((float4*)g_A)[gi] = o;
}

// ---------------------------------------------------------------------------
// Kernel 4: projection + bias + residual
// ---------------------------------------------------------------------------
__global__ __launch_bounds__(256) void proj_kernel(
    const float* __restrict__ x,
    const float* __restrict__ wp,
    const float* __restrict__ bp,
    float* __restrict__ outp) {
  float* smem = (float*)dynsmem;
  float* As = smem;               // [64][132]
  float* Ws = smem + 64*132;      // [128][128]

  int b  = blockIdx.x >> 6;
  int n0 = (blockIdx.x & 63) << 6;
  int t  = threadIdx.x;
  const float4* Ag = (const float4*)(g_A + ((size_t)b*NN + n0)*CC);

  for (int i = t; i < 64*32; i += 256) {
    int row = i >> 5, c4 = i & 31;
    *(float4*)&As[row*132 + c4*4] = Ag[i];
  }
  const float4* wsrc = (const float4*)wp;
  for (int i = t; i < 128*32; i += 256) ((float4*)Ws)[i] = wsrc[i];
  __syncthreads();

  int cgrp = t & 15;
  int wgrp = t >> 4;

  float acc[8][4];
  #pragma unroll
  for (int r = 0; r < 8; r++)
    { acc[r][0]=0.f; acc[r][1]=0.f; acc[r][2]=0.f; acc[r][3]=0.f; }

  #pragma unroll 4
  for (int ci = 0; ci < 128; ci += 4) {
    float4 a0 = *(float4*)&As[(cgrp*4+0)*132 + ci];
    float4 a1 = *(float4*)&As[(cgrp*4+1)*132 + ci];
    float4 a2 = *(float4*)&As[(cgrp*4+2)*132 + ci];
    float4 a3 = *(float4*)&As[(cgrp*4+3)*132 + ci];
    #pragma unroll
    for (int r = 0; r < 8; r++) {
      float4 w = *(float4*)&Ws[(wgrp*8+r)*128 + ci];
      acc[r][0] += w.x*a0.x + w.y*a0.y + w.z*a0.z + w.w*a0.w;
      acc[r][1] += w.x*a1.x + w.y*a1.y + w.z*a1.z + w.w*a1.w;
      acc[r][2] += w.x*a2.x + w.y*a2.y + w.z*a2.z + w.w*a2.w;
      acc[r][3] += w.x*a3.x + w.y*a3.y + w.z*a3.z + w.w*a3.w;
    }
  }

  #pragma unroll
  for (int r = 0; r < 8; r++) {
    int co = wgrp*8 + r;
    float bias = bp[co];
    size_t base = (size_t)b*CC*NN + (size_t)co*NN + n0 + cgrp*4;
    float4 xv = *(const float4*)&x[base];
    float4 o;
    o.x = xv.x + acc[r][0] + bias;
    o.y = xv.y + acc[r][1] + bias;
    o.z = xv.z + acc[r][2] + bias;
    o.w = xv.w + acc[r][3] + bias;
    *(float4*)&outp[base] = o;
  }
}

// ---------------------------------------------------------------------------
extern "C" void kernel_launch(void* const* d_in, const int* in_sizes, int n_in,
                              void* d_out, int out_size) {
  (void)in_sizes; (void)n_in; (void)out_size;
  const float* x    = (const float*)d_in[0];
  const float* gn_w = (const float*)d_in[1];
  const float* gn_b = (const float*)d_in[2];
  const float* wq   = (const float*)d_in[3];
  const float* bq   = (const float*)d_in[4];
  const float* wk   = (const float*)d_in[5];
  const float* bk   = (const float*)d_in[6];
  const float* wv   = (const float*)d_in[7];
  const float* bv   = (const float*)d_in[8];
  const float* wp   = (const float*)d_in[9];
  const float* bp   = (const float*)d_in[10];
  float* out = (float*)d_out;

  const int QKV_SMEM  = (128*64 + 128*128) * 4;   // 98304
  const int ATTN_SMEM = 32768;
  const int PROJ_SMEM = (64*132 + 128*128) * 4;   // 99328
  cudaFuncSetAttribute(qkv_kernel,  cudaFuncAttributeMaxDynamicSharedMemorySize, QKV_SMEM);
  cudaFuncSetAttribute(attn_kernel, cudaFuncAttributeMaxDynamicSharedMemorySize, ATTN_SMEM);
  cudaFuncSetAttribute(proj_kernel, cudaFuncAttributeMaxDynamicSharedMemorySize, PROJ_SMEM);

  gn_kernel<<<64, 256>>>(x, gn_w, gn_b);
  qkv_kernel<<<128, 256, QKV_SMEM>>>(wq, bq, wk, bk, wv, bv);
  attn_kernel<<<128, 256, ATTN_SMEM>>>();
  combine_kernel<<<1024, 256>>>();
  proj_kernel<<<128, 256, PROJ_SMEM>>>(x, wp, bp, out);
}

// round 8
// speedup vs baseline: 7.6863x; 1.9929x over previous
#include <cuda_runtime.h>
#include <cuda_bf16.h>
#include <stdint.h>

#define BB 2
#define CC 128
#define NN 4096
#define SCALE 0.08838834764831845f   // 128^-0.5

// ---------------- scratch (no allocations allowed) -------------------------
__device__ float          g_H [BB*CC*NN];     // groupnorm out, [b][c][n] fp32
__device__ __nv_bfloat16  g_Qh[BB*NN*CC];     // [b][n][c] bf16
__device__ __nv_bfloat16  g_Kh[BB*NN*CC];     // [b][n][c] bf16
__device__ __nv_bfloat16  g_Vh[BB*NN*CC];     // [b][n][c] bf16
__device__ float          g_Op[BB*2*NN*CC];   // partial O, [b][sp][n][c]
__device__ float          g_l [BB*2*NN];      // partial softmax sums
__device__ __nv_bfloat16  g_Ab[BB*NN*CC];     // combined attn out, [b][n][c] bf16

extern __shared__ char dynsmem[];

// ---------------- PTX helpers (baseline-safe, sm_80-era) -------------------
__device__ __forceinline__ uint32_t smem_u32(const void* p) {
  uint32_t a;
  asm("{ .reg .u64 t; cvta.to.shared.u64 t, %1; cvt.u32.u64 %0, t; }"
      : "=r"(a) : "l"(p));
  return a;
}
__device__ __forceinline__ void ldsm_x4(uint32_t& r0, uint32_t& r1,
                                        uint32_t& r2, uint32_t& r3, uint32_t a) {
  asm volatile("ldmatrix.sync.aligned.m8n8.x4.shared.b16 {%0,%1,%2,%3}, [%4];"
               : "=r"(r0), "=r"(r1), "=r"(r2), "=r"(r3) : "r"(a));
}
__device__ __forceinline__ void ldsm_x4_t(uint32_t& r0, uint32_t& r1,
                                          uint32_t& r2, uint32_t& r3, uint32_t a) {
  asm volatile("ldmatrix.sync.aligned.m8n8.x4.trans.shared.b16 {%0,%1,%2,%3}, [%4];"
               : "=r"(r0), "=r"(r1), "=r"(r2), "=r"(r3) : "r"(a));
}
__device__ __forceinline__ void ldsm_x2(uint32_t& r0, uint32_t& r1, uint32_t a) {
  asm volatile("ldmatrix.sync.aligned.m8n8.x2.shared.b16 {%0,%1}, [%2];"
               : "=r"(r0), "=r"(r1) : "r"(a));
}
__device__ __forceinline__ void ldsm_x2_t(uint32_t& r0, uint32_t& r1, uint32_t a) {
  asm volatile("ldmatrix.sync.aligned.m8n8.x2.trans.shared.b16 {%0,%1}, [%2];"
               : "=r"(r0), "=r"(r1) : "r"(a));
}
__device__ __forceinline__ void mma_bf16(float* d, const uint32_t* a,
                                         const uint32_t* b, const float* c) {
  asm volatile(
    "mma.sync.aligned.m16n8k16.row.col.f32.bf16.bf16.f32 "
    "{%0,%1,%2,%3}, {%4,%5,%6,%7}, {%8,%9}, {%10,%11,%12,%13};"
    : "=f"(d[0]), "=f"(d[1]), "=f"(d[2]), "=f"(d[3])
    : "r"(a[0]), "r"(a[1]), "r"(a[2]), "r"(a[3]),
      "r"(b[0]), "r"(b[1]),
      "f"(c[0]), "f"(c[1]), "f"(c[2]), "f"(c[3]));
}
__device__ __forceinline__ uint32_t pk2(float lo, float hi) {
  uint32_t r;
  asm("cvt.rn.bf16x2.f32 %0, %1, %2;" : "=r"(r) : "f"(hi), "f"(lo));
  return r;
}
__device__ __forceinline__ void cpa16(uint32_t dst, const void* src) {
  asm volatile("cp.async.cg.shared.global [%0], [%1], 16;" :: "r"(dst), "l"(src));
}
__device__ __forceinline__ void cp_commit() {
  asm volatile("cp.async.commit_group;" ::: "memory");
}
template <int N> __device__ __forceinline__ void cp_wait() {
  asm volatile("cp.async.wait_group %0;" :: "n"(N) : "memory");
}

// ---------------------------------------------------------------------------
// Kernel 1: GroupNorm
// ---------------------------------------------------------------------------
__global__ __launch_bounds__(256) void gn_kernel(
    const float* __restrict__ x,
    const float* __restrict__ gamma,
    const float* __restrict__ beta) {
  int b = blockIdx.x >> 5;
  int g = blockIdx.x & 31;
  const float4* xp = (const float4*)(x + ((size_t)b*CC + g*4)*NN);
  float s = 0.f, s2 = 0.f;
  for (int i = threadIdx.x; i < 4096; i += 256) {
    float4 v = xp[i];
    s  += v.x + v.y + v.z + v.w;
    s2 += v.x*v.x + v.y*v.y + v.z*v.z + v.w*v.w;
  }
  #pragma unroll
  for (int o = 16; o; o >>= 1) {
    s  += __shfl_xor_sync(0xffffffffu, s, o);
    s2 += __shfl_xor_sync(0xffffffffu, s2, o);
  }
  __shared__ float rs[8], rs2[8];
  __shared__ float s_mean, s_rstd;
  int wid = threadIdx.x >> 5;
  if ((threadIdx.x & 31) == 0) { rs[wid] = s; rs2[wid] = s2; }
  __syncthreads();
  if (threadIdx.x == 0) {
    float S = 0.f, S2 = 0.f;
    #pragma unroll
    for (int i = 0; i < 8; i++) { S += rs[i]; S2 += rs2[i]; }
    float mean = S * (1.f/16384.f);
    float var  = S2 * (1.f/16384.f) - mean*mean;
    s_mean = mean;
    s_rstd = rsqrtf(var + 1e-5f);
  }
  __syncthreads();
  float mean = s_mean, rstd = s_rstd;
  float* hp = g_H + ((size_t)b*CC + g*4)*NN;
  for (int i = threadIdx.x; i < 4096; i += 256) {
    int c = g*4 + (i >> 10);
    float ga = gamma[c] * rstd;
    float be = beta[c] - mean * ga;
    float4 v = xp[i];
    float4 o;
    o.x = v.x*ga + be; o.y = v.y*ga + be; o.z = v.z*ga + be; o.w = v.w*ga + be;
    ((float4*)hp)[i] = o;
  }
}

// ---------------------------------------------------------------------------
// Kernel 2: fused Q/K/V GEMM, HMMA. grid = BB*32 (128-token tiles), 256 thr.
// A = H^T [n][c] via ldmatrix.trans from Hs[c][n]; B = W[co][c] non-trans.
// SMEM: Hs [128c][256B] swizzled @0, Ws [128co][256B] @32768. 64KB.
// ---------------------------------------------------------------------------
__global__ __launch_bounds__(256) void qkv_kernel(
    const float* __restrict__ wq, const float* __restrict__ bq,
    const float* __restrict__ wk, const float* __restrict__ bk,
    const float* __restrict__ wv, const float* __restrict__ bv) {
  char* smem = dynsmem;
  uint32_t sb = smem_u32(smem);
  uint32_t sbW = sb + 32768;

  int b  = blockIdx.x >> 5;
  int n0 = (blockIdx.x & 31) << 7;
  int t  = threadIdx.x;
  int w  = t >> 5;
  int lane = t & 31;

  // stage H tile [c][n0..n0+128) fp32 -> bf16, swizzled
  const float* Hg = g_H + (size_t)b*CC*NN;
  for (int i = t; i < 2048; i += 256) {
    int c = i >> 4, j8 = i & 15;
    const float4* hp = (const float4*)(Hg + (size_t)c*NN + n0 + j8*8);
    float4 f0 = hp[0], f1 = hp[1];
    uint4 o;
    o.x = pk2(f0.x, f0.y); o.y = pk2(f0.z, f0.w);
    o.z = pk2(f1.x, f1.y); o.w = pk2(f1.z, f1.w);
    *(uint4*)(smem + c*256 + ((j8 ^ (c & 7)) << 4)) = o;
  }
  __syncthreads();

  // A-fragments of H^T (rows n = w*16..+16, k = c) via trans ldmatrix
  uint32_t qa[8][4];
  {
    int krow_lo = ((lane >> 4) << 3) + (lane & 7);
    int mcol    = w*16 + (((lane >> 3) & 1) << 3);
    int mch     = mcol >> 3;
    #pragma unroll
    for (int ks = 0; ks < 8; ks++) {
      int krow = ks*16 + krow_lo;
      uint32_t a = sb + krow*256 + ((mch ^ (krow & 7)) << 4);
      ldsm_x4_t(qa[ks][0], qa[ks][1], qa[ks][2], qa[ks][3], a);
    }
  }

  const float* Wp[3] = {wq, wk, wv};
  const float* Bp[3] = {bq, bk, bv};
  __nv_bfloat16* Op[3] = {g_Qh + (size_t)b*NN*CC, g_Kh + (size_t)b*NN*CC,
                          g_Vh + (size_t)b*NN*CC};

  int rl = lane & 7;
  int hf = (lane >> 3) & 1;
  int n_r = n0 + w*16 + (lane >> 2);

  for (int m = 0; m < 3; m++) {
    __syncthreads();
    const float* wsrc = Wp[m];
    for (int i = t; i < 2048; i += 256) {
      int co = i >> 4, j8 = i & 15;
      const float4* pw = (const float4*)(wsrc + co*CC + j8*8);
      float4 f0 = pw[0], f1 = pw[1];
      uint4 o;
      o.x = pk2(f0.x, f0.y); o.y = pk2(f0.z, f0.w);
      o.z = pk2(f1.x, f1.y); o.w = pk2(f1.z, f1.w);
      *(uint4*)(smem + 32768 + co*256 + ((j8 ^ (co & 7)) << 4)) = o;
    }
    __syncthreads();

    __nv_bfloat16* out = Op[m];
    const float* bias = Bp[m];
    #pragma unroll
    for (int nb = 0; nb < 16; nb++) {
      float acc[4] = {0.f, 0.f, 0.f, 0.f};
      #pragma unroll
      for (int ks = 0; ks < 8; ks++) {
        uint32_t bb[2];
        uint32_t a = sbW + (nb*8 + rl)*256 + (((2*ks + hf) ^ rl) << 4);
        ldsm_x2(bb[0], bb[1], a);
        mma_bf16(acc, qa[ks], bb, acc);
      }
      int co0 = nb*8 + (lane & 3)*2;
      float b0 = bias[co0], b1 = bias[co0 + 1];
      *(uint32_t*)(out + (size_t)n_r*CC + co0)       = pk2(acc[0]+b0, acc[1]+b1);
      *(uint32_t*)(out + (size_t)(n_r+8)*CC + co0)   = pk2(acc[2]+b0, acc[3]+b1);
    }
  }
}

// ---------------------------------------------------------------------------
// Kernel 3: bf16 HMMA flash attention, cp.async double-buffered K/V.
// grid = BB*32*2 = 128 CTAs, 256 thr. V in [n][c], PV B-frags via ldsm trans.
// SMEM: buf0 K|V @0 (32KB), buf1 K|V @32768 (32KB). Q staged in buf1.
// ---------------------------------------------------------------------------
__global__ __launch_bounds__(256) void attn_kernel() {
  char* smem = dynsmem;
  uint32_t sb = smem_u32(smem);

  int t    = threadIdx.x;
  int w    = t >> 5;
  int lane = t & 31;
  int bid  = blockIdx.x;
  int b    = bid >> 6;
  int qt   = (bid >> 1) & 31;
  int sp   = bid & 1;
  int q0   = qt << 7;
  int kb0  = sp << 11;

  const __nv_bfloat16* Kg = g_Kh + (size_t)b*NN*CC;
  const __nv_bfloat16* Vg = g_Vh + (size_t)b*NN*CC;

  // ---- stage Q tile (swizzled) into buf1, load A-fragments ----
  for (int i = t; i < 2048; i += 256) {
    int row = i >> 4, cb = i & 15;
    *(uint4*)(smem + 32768 + row*256 + ((cb ^ (row & 7)) << 4)) =
        *(const uint4*)(g_Qh + ((size_t)b*NN + q0 + row)*CC + cb*8);
  }
  __syncthreads();

  // prefetch tile 0 into buf0 while Q frags load from buf1
  {
    int kb = kb0;
    for (int i = t; i < 1024; i += 256) {
      int row = i >> 4, cb = i & 15;
      uint32_t d = sb + row*256 + ((cb ^ (row & 7)) << 4);
      cpa16(d,          Kg + ((size_t)(kb + row))*CC + cb*8);
      cpa16(d + 16384,  Vg + ((size_t)(kb + row))*CC + cb*8);
    }
    cp_commit();
  }

  uint32_t qa[8][4];
  {
    int row = w*16 + (lane & 15);
    int kc  = (lane >> 4) & 1;
    #pragma unroll
    for (int ks = 0; ks < 8; ks++) {
      uint32_t a = sb + 32768 + row*256 + (((2*ks + kc) ^ (row & 7)) << 4);
      ldsm_x4(qa[ks][0], qa[ks][1], qa[ks][2], qa[ks][3], a);
    }
  }
  __syncthreads();   // Q frags in regs; buf1 free

  // prefetch tile 1 into buf1
  {
    int kb = kb0 + 64;
    for (int i = t; i < 1024; i += 256) {
      int row = i >> 4, cb = i & 15;
      uint32_t d = sb + 32768 + row*256 + ((cb ^ (row & 7)) << 4);
      cpa16(d,          Kg + ((size_t)(kb + row))*CC + cb*8);
      cpa16(d + 16384,  Vg + ((size_t)(kb + row))*CC + cb*8);
    }
    cp_commit();
  }

  int rl = lane & 7;
  int hf = (lane >> 3) & 1;

  float oacc[16][4];
  #pragma unroll
  for (int nb = 0; nb < 16; nb++)
    { oacc[nb][0]=0.f; oacc[nb][1]=0.f; oacc[nb][2]=0.f; oacc[nb][3]=0.f; }
  float l0 = 0.f, l1 = 0.f;

  for (int kt = 0; kt < 32; kt++) {
    if (kt < 31) cp_wait<1>(); else cp_wait<0>();
    __syncthreads();

    uint32_t Ks = sb + (uint32_t)(kt & 1)*32768;
    uint32_t Vs = Ks + 16384;

    // ---- S = Q K^T ----
    float sacc[8][4];
    #pragma unroll
    for (int nb = 0; nb < 8; nb++) {
      sacc[nb][0]=0.f; sacc[nb][1]=0.f; sacc[nb][2]=0.f; sacc[nb][3]=0.f;
      #pragma unroll
      for (int ks = 0; ks < 8; ks++) {
        uint32_t bb[2];
        uint32_t a = Ks + ((nb*8 + rl) << 8) + (((2*ks + hf) ^ rl) << 4);
        ldsm_x2(bb[0], bb[1], a);
        mma_bf16(sacc[nb], qa[ks], bb, sacc[nb]);
      }
    }

    // ---- exp + row sums ----
    float rs0 = 0.f, rs1 = 0.f;
    #pragma unroll
    for (int nb = 0; nb < 8; nb++) {
      float p0 = __expf(fminf(sacc[nb][0]*SCALE, 80.f));
      float p1 = __expf(fminf(sacc[nb][1]*SCALE, 80.f));
      float p2 = __expf(fminf(sacc[nb][2]*SCALE, 80.f));
      float p3 = __expf(fminf(sacc[nb][3]*SCALE, 80.f));
      sacc[nb][0]=p0; sacc[nb][1]=p1; sacc[nb][2]=p2; sacc[nb][3]=p3;
      rs0 += p0 + p1;
      rs1 += p2 + p3;
    }
    rs0 += __shfl_xor_sync(0xffffffffu, rs0, 1);
    rs0 += __shfl_xor_sync(0xffffffffu, rs0, 2);
    rs1 += __shfl_xor_sync(0xffffffffu, rs1, 1);
    rs1 += __shfl_xor_sync(0xffffffffu, rs1, 2);
    l0 += rs0;
    l1 += rs1;

    // ---- O += P V  (B-frags via trans ldmatrix from V[key][ch]) ----
    #pragma unroll
    for (int ks = 0; ks < 4; ks++) {
      uint32_t pa[4];
      pa[0] = pk2(sacc[2*ks][0],   sacc[2*ks][1]);
      pa[1] = pk2(sacc[2*ks][2],   sacc[2*ks][3]);
      pa[2] = pk2(sacc[2*ks+1][0], sacc[2*ks+1][1]);
      pa[3] = pk2(sacc[2*ks+1][2], sacc[2*ks+1][3]);
      int vrow = ks*16 + (lane & 15);
      uint32_t abase = Vs + vrow*256;
      uint32_t sw = (uint32_t)(vrow & 7) << 4;
      #pragma unroll
      for (int nb = 0; nb < 16; nb++) {
        uint32_t bb[2];
        uint32_t a = abase + (((uint32_t)(nb << 4)) ^ sw);
        ldsm_x2_t(bb[0], bb[1], a);
        mma_bf16(oacc[nb], pa, bb, oacc[nb]);
      }
    }

    __syncthreads();   // compute done; buf[kt&1] free for prefetch kt+2
    if (kt + 2 < 32) {
      int kb = kb0 + ((kt + 2) << 6);
      uint32_t base = sb + (uint32_t)(kt & 1)*32768;
      for (int i = t; i < 1024; i += 256) {
        int row = i >> 4, cb = i & 15;
        uint32_t d = base + row*256 + ((cb ^ (row & 7)) << 4);
        cpa16(d,          Kg + ((size_t)(kb + row))*CC + cb*8);
        cpa16(d + 16384,  Vg + ((size_t)(kb + row))*CC + cb*8);
      }
      cp_commit();
    }
  }

  // ---- epilogue: partial O and l ----
  int r0 = q0 + w*16 + (lane >> 2);
  float* Og = g_Op + ((size_t)(b*2 + sp)*NN + r0)*CC;
  int col = (lane & 3)*2;
  #pragma unroll
  for (int nb = 0; nb < 16; nb++) {
    float2 v0 = {oacc[nb][0], oacc[nb][1]};
    float2 v1 = {oacc[nb][2], oacc[nb][3]};
    *(float2*)(Og + nb*8 + col)                = v0;
    *(float2*)(Og + (size_t)8*CC + nb*8 + col) = v1;
  }
  if ((lane & 3) == 0) {
    g_l[(size_t)(b*2 + sp)*NN + r0]     = l0;
    g_l[(size_t)(b*2 + sp)*NN + r0 + 8] = l1;
  }
}

// ---------------------------------------------------------------------------
// Kernel 3b: combine split-KV partials -> g_Ab [b][n][c] bf16
// ---------------------------------------------------------------------------
__global__ __launch_bounds__(256) void combine_kernel() {
  int gi  = blockIdx.x * 256 + threadIdx.x;   // float4 index over [B][N][C]
  int ngl = gi >> 5;                          // b*NN + n
  int b   = ngl >> 12;
  int n   = ngl & 4095;
  float l = g_l[(size_t)(b*2)*NN + n] + g_l[(size_t)(b*2+1)*NN + n];
  float inv = 1.f / l;
  const float4* O = (const float4*)g_Op;
  float4 a = O[gi + (size_t)b*131072];
  float4 c = O[gi + (size_t)b*131072 + 131072];
  uint2 o;
  o.x = pk2((a.x + c.x)*inv, (a.y + c.y)*inv);
  o.y = pk2((a.z + c.z)*inv, (a.w + c.w)*inv);
  ((uint2*)g_Ab)[gi] = o;
}

// ---------------------------------------------------------------------------
// Kernel 4: projection + bias + residual, HMMA. grid = BB*32, 256 thr.
// A = g_Ab [n][c] (non-trans, like attn Q); B = wp[co][c].
// Epilogue transposes via SMEM to [co][n] with residual.
// SMEM: As 32KB @0, Ws 32KB @32768 (compute); Ot [128][132]f @0 (66KB, epi).
// ---------------------------------------------------------------------------
__global__ __launch_bounds__(256) void proj_kernel(
    const float* __restrict__ x,
    const float* __restrict__ wp,
    const float* __restrict__ bp,
    float* __restrict__ outp) {
  char* smem = dynsmem;
  uint32_t sb = smem_u32(smem);
  uint32_t sbW = sb + 32768;
  float* Ot = (float*)smem;

  int b  = blockIdx.x >> 5;
  int n0 = (blockIdx.x & 31) << 7;
  int t  = threadIdx.x;
  int w  = t >> 5;
  int lane = t & 31;

  // stage A tile [n][c] bf16 (already bf16 in gmem)
  for (int i = t; i < 2048; i += 256) {
    int row = i >> 4, cb = i & 15;
    *(uint4*)(smem + row*256 + ((cb ^ (row & 7)) << 4)) =
        *(const uint4*)(g_Ab + ((size_t)b*NN + n0 + row)*CC + cb*8);
  }
  // stage wp fp32 -> bf16
  for (int i = t; i < 2048; i += 256) {
    int co = i >> 4, j8 = i & 15;
    const float4* pw = (const float4*)(wp + co*CC + j8*8);
    float4 f0 = pw[0], f1 = pw[1];
    uint4 o;
    o.x = pk2(f0.x, f0.y); o.y = pk2(f0.z, f0.w);
    o.z = pk2(f1.x, f1.y); o.w = pk2(f1.z, f1.w);
    *(uint4*)(smem + 32768 + co*256 + ((j8 ^ (co & 7)) << 4)) = o;
  }
  __syncthreads();

  // A-fragments (rows n)
  uint32_t qa[8][4];
  {
    int row = w*16 + (lane & 15);
    int kc  = (lane >> 4) & 1;
    #pragma unroll
    for (int ks = 0; ks < 8; ks++) {
      uint32_t a = sb + row*256 + (((2*ks + kc) ^ (row & 7)) << 4);
      ldsm_x4(qa[ks][0], qa[ks][1], qa[ks][2], qa[ks][3], a);
    }
  }

  int rl = lane & 7;
  int hf = (lane >> 3) & 1;

  float acc[16][4];
  #pragma unroll
  for (int nb = 0; nb < 16; nb++) {
    acc[nb][0]=0.f; acc[nb][1]=0.f; acc[nb][2]=0.f; acc[nb][3]=0.f;
    #pragma unroll
    for (int ks = 0; ks < 8; ks++) {
      uint32_t bb[2];
      uint32_t a = sbW + (nb*8 + rl)*256 + (((2*ks + hf) ^ rl) << 4);
      ldsm_x2(bb[0], bb[1], a);
      mma_bf16(acc[nb], qa[ks], bb, acc[nb]);
    }
  }
  __syncthreads();   // done reading As/Ws; reuse smem as Ot[128co][132]

  int nl = w*16 + (lane >> 2);
  #pragma unroll
  for (int nb = 0; nb < 16; nb++) {
    int co0 = nb*8 + (lane & 3)*2;
    Ot[co0*132 + nl]           = acc[nb][0];
    Ot[(co0 + 1)*132 + nl]     = acc[nb][1];
    Ot[co0*132 + nl + 8]       = acc[nb][2];
    Ot[(co0 + 1)*132 + nl + 8] = acc[nb][3];
  }
  __syncthreads();

  // coalesced output: out[b][co][n0..n0+128) = x + Ot + bias
  for (int i = t; i < 4096; i += 256) {
    int co = i >> 5, q = i & 31;
    float bias = bp[co];
    size_t base = (size_t)b*CC*NN + (size_t)co*NN + n0 + q*4;
    float4 xv = *(const float4*)&x[base];
    float4 hv = *(float4*)&Ot[co*132 + q*4];
    float4 o;
    o.x = xv.x + hv.x + bias;
    o.y = xv.y + hv.y + bias;
    o.z = xv.z + hv.z + bias;
    o.w = xv.w + hv.w + bias;
    *(float4*)&outp[base] = o;
  }
}

// ---------------------------------------------------------------------------
extern "C" void kernel_launch(void* const* d_in, const int* in_sizes, int n_in,
                              void* d_out, int out_size) {
  (void)in_sizes; (void)n_in; (void)out_size;
  const float* x    = (const float*)d_in[0];
  const float* gn_w = (const float*)d_in[1];
  const float* gn_b = (const float*)d_in[2];
  const float* wq   = (const float*)d_in[3];
  const float* bq   = (const float*)d_in[4];
  const float* wk   = (const float*)d_in[5];
  const float* bk   = (const float*)d_in[6];
  const float* wv   = (const float*)d_in[7];
  const float* bv   = (const float*)d_in[8];
  const float* wp   = (const float*)d_in[9];
  const float* bp   = (const float*)d_in[10];
  float* out = (float*)d_out;

  const int QKV_SMEM  = 65536;
  const int ATTN_SMEM = 65536;
  const int PROJ_SMEM = 128*132*4;   // 67584
  cudaFuncSetAttribute(qkv_kernel,  cudaFuncAttributeMaxDynamicSharedMemorySize, QKV_SMEM);
  cudaFuncSetAttribute(attn_kernel, cudaFuncAttributeMaxDynamicSharedMemorySize, ATTN_SMEM);
  cudaFuncSetAttribute(proj_kernel, cudaFuncAttributeMaxDynamicSharedMemorySize, PROJ_SMEM);

  gn_kernel<<<64, 256>>>(x, gn_w, gn_b);
  qkv_kernel<<<64, 256, QKV_SMEM>>>(wq, bq, wk, bk, wv, bv);
  attn_kernel<<<128, 256, ATTN_SMEM>>>();
  combine_kernel<<<1024, 256>>>();
  proj_kernel<<<64, 256, PROJ_SMEM>>>(x, wp, bp, out);
}

// round 9
// speedup vs baseline: 7.8396x; 1.0199x over previous
#include <cuda_runtime.h>
#include <cuda_bf16.h>
#include <stdint.h>

#define BB 2
#define CC 128
#define NN 4096
#define SCALE 0.08838834764831845f   // 128^-0.5

// ---------------- scratch (no allocations allowed) -------------------------
__device__ float2         g_stats[BB*32];      // per (b,group): mean, rstd
__device__ __nv_bfloat16  g_Qh[BB*NN*CC];      // [b][n][c] bf16
__device__ __nv_bfloat16  g_Kh[BB*NN*CC];      // [b][n][c] bf16
__device__ __nv_bfloat16  g_Vh[BB*NN*CC];      // [b][n][c] bf16
__device__ __nv_bfloat16  g_Opb[BB*2*NN*CC];   // partial O, [b][sp][n][c] bf16
__device__ float          g_l [BB*2*NN];       // partial softmax sums
__device__ __nv_bfloat16  g_Ab[BB*NN*CC];      // combined attn out, [b][n][c] bf16

extern __shared__ char dynsmem[];

// ---------------- PTX helpers (baseline-safe, sm_80-era) -------------------
__device__ __forceinline__ uint32_t smem_u32(const void* p) {
  uint32_t a;
  asm("{ .reg .u64 t; cvta.to.shared.u64 t, %1; cvt.u32.u64 %0, t; }"
      : "=r"(a) : "l"(p));
  return a;
}
__device__ __forceinline__ void ldsm_x4(uint32_t& r0, uint32_t& r1,
                                        uint32_t& r2, uint32_t& r3, uint32_t a) {
  asm volatile("ldmatrix.sync.aligned.m8n8.x4.shared.b16 {%0,%1,%2,%3}, [%4];"
               : "=r"(r0), "=r"(r1), "=r"(r2), "=r"(r3) : "r"(a));
}
__device__ __forceinline__ void ldsm_x4_t(uint32_t& r0, uint32_t& r1,
                                          uint32_t& r2, uint32_t& r3, uint32_t a) {
  asm volatile("ldmatrix.sync.aligned.m8n8.x4.trans.shared.b16 {%0,%1,%2,%3}, [%4];"
               : "=r"(r0), "=r"(r1), "=r"(r2), "=r"(r3) : "r"(a));
}
__device__ __forceinline__ void ldsm_x4_tr(uint32_t& r0, uint32_t& r1,
                                           uint32_t& r2, uint32_t& r3, uint32_t a) {
  asm volatile("ldmatrix.sync.aligned.m8n8.x4.trans.shared.b16 {%0,%1,%2,%3}, [%4];"
               : "=r"(r0), "=r"(r1), "=r"(r2), "=r"(r3) : "r"(a));
}
__device__ __forceinline__ void mma_bf16(float* d, const uint32_t* a,
                                         const uint32_t* b, const float* c) {
  asm volatile(
    "mma.sync.aligned.m16n8k16.row.col.f32.bf16.bf16.f32 "
    "{%0,%1,%2,%3}, {%4,%5,%6,%7}, {%8,%9}, {%10,%11,%12,%13};"
    : "=f"(d[0]), "=f"(d[1]), "=f"(d[2]), "=f"(d[3])
    : "r"(a[0]), "r"(a[1]), "r"(a[2]), "r"(a[3]),
      "r"(b[0]), "r"(b[1]),
      "f"(c[0]), "f"(c[1]), "f"(c[2]), "f"(c[3]));
}
__device__ __forceinline__ uint32_t pk2(float lo, float hi) {
  uint32_t r;
  asm("cvt.rn.bf16x2.f32 %0, %1, %2;" : "=r"(r) : "f"(hi), "f"(lo));
  return r;
}
__device__ __forceinline__ void cpa16(uint32_t dst, const void* src) {
  asm volatile("cp.async.cg.shared.global [%0], [%1], 16;" :: "r"(dst), "l"(src));
}
__device__ __forceinline__ void cp_commit() {
  asm volatile("cp.async.commit_group;" ::: "memory");
}
template <int N> __device__ __forceinline__ void cp_wait() {
  asm volatile("cp.async.wait_group %0;" :: "n"(N) : "memory");
}

// ---------------------------------------------------------------------------
// Kernel 1: GroupNorm stats only. 64 blocks = (b, group).
// ---------------------------------------------------------------------------
__global__ __launch_bounds__(256) void gn_stats_kernel(const float* __restrict__ x) {
  int b = blockIdx.x >> 5;
  int g = blockIdx.x & 31;
  const float4* xp = (const float4*)(x + ((size_t)b*CC + g*4)*NN);
  float s = 0.f, s2 = 0.f;
  for (int i = threadIdx.x; i < 4096; i += 256) {
    float4 v = xp[i];
    s  += v.x + v.y + v.z + v.w;
    s2 += v.x*v.x + v.y*v.y + v.z*v.z + v.w*v.w;
  }
  #pragma unroll
  for (int o = 16; o; o >>= 1) {
    s  += __shfl_xor_sync(0xffffffffu, s, o);
    s2 += __shfl_xor_sync(0xffffffffu, s2, o);
  }
  __shared__ float rs[8], rs2[8];
  int wid = threadIdx.x >> 5;
  if ((threadIdx.x & 31) == 0) { rs[wid] = s; rs2[wid] = s2; }
  __syncthreads();
  if (threadIdx.x == 0) {
    float S = 0.f, S2 = 0.f;
    #pragma unroll
    for (int i = 0; i < 8; i++) { S += rs[i]; S2 += rs2[i]; }
    float mean = S * (1.f/16384.f);
    float var  = S2 * (1.f/16384.f) - mean*mean;
    g_stats[blockIdx.x] = make_float2(mean, rsqrtf(var + 1e-5f));
  }
}

// ---------------------------------------------------------------------------
// Kernel 2: fused GN-apply + Q/K/V GEMM, HMMA. grid = BB*32, 256 thr.
// Stages normalized H (from x + stats) as bf16 [c][n] swizzled.
// A = H^T via ldmatrix.trans; B = W[co][c] non-trans, ldsm x4-batched.
// ---------------------------------------------------------------------------
__global__ __launch_bounds__(256) void qkv_kernel(
    const float* __restrict__ x,
    const float* __restrict__ gamma, const float* __restrict__ beta,
    const float* __restrict__ wq, const float* __restrict__ bq,
    const float* __restrict__ wk, const float* __restrict__ bk,
    const float* __restrict__ wv, const float* __restrict__ bv) {
  char* smem = dynsmem;
  uint32_t sb = smem_u32(smem);
  uint32_t sbW = sb + 32768;

  int b  = blockIdx.x >> 5;
  int n0 = (blockIdx.x & 31) << 7;
  int t  = threadIdx.x;
  int w  = t >> 5;
  int lane = t & 31;

  // stage normalized H tile [c][n0..n0+128) -> bf16, swizzled
  for (int i = t; i < 2048; i += 256) {
    int c = i >> 4, j8 = i & 15;
    float2 st = g_stats[b*32 + (c >> 2)];
    float ga = gamma[c] * st.y;
    float be = beta[c] - st.x * ga;
    const float4* hp = (const float4*)(x + ((size_t)b*CC + c)*NN + n0 + j8*8);
    float4 f0 = hp[0], f1 = hp[1];
    uint4 o;
    o.x = pk2(f0.x*ga+be, f0.y*ga+be); o.y = pk2(f0.z*ga+be, f0.w*ga+be);
    o.z = pk2(f1.x*ga+be, f1.y*ga+be); o.w = pk2(f1.z*ga+be, f1.w*ga+be);
    *(uint4*)(smem + c*256 + ((j8 ^ (c & 7)) << 4)) = o;
  }
  __syncthreads();

  // A-fragments of H^T (rows n, k = c) via trans ldmatrix
  uint32_t qa[8][4];
  {
    int krow_lo = ((lane >> 4) << 3) + (lane & 7);
    int mcol    = w*16 + (((lane >> 3) & 1) << 3);
    int mch     = mcol >> 3;
    #pragma unroll
    for (int ks = 0; ks < 8; ks++) {
      int krow = ks*16 + krow_lo;
      uint32_t a = sb + krow*256 + ((mch ^ (krow & 7)) << 4);
      ldsm_x4_t(qa[ks][0], qa[ks][1], qa[ks][2], qa[ks][3], a);
    }
  }

  const float* Wp[3] = {wq, wk, wv};
  const float* Bp[3] = {bq, bk, bv};
  __nv_bfloat16* Op[3] = {g_Qh + (size_t)b*NN*CC, g_Kh + (size_t)b*NN*CC,
                          g_Vh + (size_t)b*NN*CC};

  int rl   = lane & 7;
  int hf   = (lane >> 3) & 1;
  int nsel = (lane >> 4) & 1;
  int n_r  = n0 + w*16 + (lane >> 2);

  for (int m = 0; m < 3; m++) {
    __syncthreads();
    const float* wsrc = Wp[m];
    for (int i = t; i < 2048; i += 256) {
      int co = i >> 4, j8 = i & 15;
      const float4* pw = (const float4*)(wsrc + co*CC + j8*8);
      float4 f0 = pw[0], f1 = pw[1];
      uint4 o;
      o.x = pk2(f0.x, f0.y); o.y = pk2(f0.z, f0.w);
      o.z = pk2(f1.x, f1.y); o.w = pk2(f1.z, f1.w);
      *(uint4*)(smem + 32768 + co*256 + ((j8 ^ (co & 7)) << 4)) = o;
    }
    __syncthreads();

    __nv_bfloat16* out = Op[m];
    const float* bias = Bp[m];
    #pragma unroll
    for (int nb = 0; nb < 16; nb += 2) {
      float a0[4] = {0.f,0.f,0.f,0.f};
      float a1[4] = {0.f,0.f,0.f,0.f};
      #pragma unroll
      for (int ks = 0; ks < 8; ks++) {
        uint32_t bb[4];
        uint32_t a = sbW + ((nb + nsel)*8 + rl)*256 + (((2*ks + hf) ^ rl) << 4);
        ldsm_x4(bb[0], bb[1], bb[2], bb[3], a);
        mma_bf16(a0, qa[ks], bb,     a0);
        mma_bf16(a1, qa[ks], bb + 2, a1);
      }
      #pragma unroll
      for (int u = 0; u < 2; u++) {
        float* ac = u ? a1 : a0;
        int co0 = (nb + u)*8 + (lane & 3)*2;
        float b0 = bias[co0], b1 = bias[co0 + 1];
        *(uint32_t*)(out + (size_t)n_r*CC + co0)     = pk2(ac[0]+b0, ac[1]+b1);
        *(uint32_t*)(out + (size_t)(n_r+8)*CC + co0) = pk2(ac[2]+b0, ac[3]+b1);
      }
    }
  }
}

// ---------------------------------------------------------------------------
// Kernel 3: bf16 HMMA flash attention, cp.async double-buffered K/V,
// x4-batched ldmatrix. grid = 128 CTAs, 256 thr.
// ---------------------------------------------------------------------------
__global__ __launch_bounds__(256) void attn_kernel() {
  char* smem = dynsmem;
  uint32_t sb = smem_u32(smem);

  int t    = threadIdx.x;
  int w    = t >> 5;
  int lane = t & 31;
  int bid  = blockIdx.x;
  int b    = bid >> 6;
  int qt   = (bid >> 1) & 31;
  int sp   = bid & 1;
  int q0   = qt << 7;
  int kb0  = sp << 11;

  const __nv_bfloat16* Kg = g_Kh + (size_t)b*NN*CC;
  const __nv_bfloat16* Vg = g_Vh + (size_t)b*NN*CC;

  // ---- stage Q tile (swizzled) into buf1, load A-fragments ----
  for (int i = t; i < 2048; i += 256) {
    int row = i >> 4, cb = i & 15;
    *(uint4*)(smem + 32768 + row*256 + ((cb ^ (row & 7)) << 4)) =
        *(const uint4*)(g_Qh + ((size_t)b*NN + q0 + row)*CC + cb*8);
  }
  __syncthreads();

  // prefetch tile 0 into buf0
  {
    int kb = kb0;
    for (int i = t; i < 1024; i += 256) {
      int row = i >> 4, cb = i & 15;
      uint32_t d = sb + row*256 + ((cb ^ (row & 7)) << 4);
      cpa16(d,          Kg + ((size_t)(kb + row))*CC + cb*8);
      cpa16(d + 16384,  Vg + ((size_t)(kb + row))*CC + cb*8);
    }
    cp_commit();
  }

  uint32_t qa[8][4];
  {
    int row = w*16 + (lane & 15);
    int kc  = (lane >> 4) & 1;
    #pragma unroll
    for (int ks = 0; ks < 8; ks++) {
      uint32_t a = sb + 32768 + row*256 + (((2*ks + kc) ^ (row & 7)) << 4);
      ldsm_x4(qa[ks][0], qa[ks][1], qa[ks][2], qa[ks][3], a);
    }
  }
  __syncthreads();   // Q frags in regs; buf1 free

  // prefetch tile 1 into buf1
  {
    int kb = kb0 + 64;
    for (int i = t; i < 1024; i += 256) {
      int row = i >> 4, cb = i & 15;
      uint32_t d = sb + 32768 + row*256 + ((cb ^ (row & 7)) << 4);
      cpa16(d,          Kg + ((size_t)(kb + row))*CC + cb*8);
      cpa16(d + 16384,  Vg + ((size_t)(kb + row))*CC + cb*8);
    }
    cp_commit();
  }

  int rl   = lane & 7;
  int hf   = (lane >> 3) & 1;
  int nsel = (lane >> 4) & 1;

  float oacc[16][4];
  #pragma unroll
  for (int nb = 0; nb < 16; nb++)
    { oacc[nb][0]=0.f; oacc[nb][1]=0.f; oacc[nb][2]=0.f; oacc[nb][3]=0.f; }
  float l0 = 0.f, l1 = 0.f;

  for (int kt = 0; kt < 32; kt++) {
    if (kt < 31) cp_wait<1>(); else cp_wait<0>();
    __syncthreads();

    uint32_t Ks = sb + (uint32_t)(kt & 1)*32768;
    uint32_t Vs = Ks + 16384;

    // ---- S = Q K^T (x4-batched B loads: two key-blocks per ldsm) ----
    float sacc[8][4];
    #pragma unroll
    for (int nb = 0; nb < 8; nb += 2) {
      float* s0 = sacc[nb];
      float* s1 = sacc[nb+1];
      s0[0]=0.f; s0[1]=0.f; s0[2]=0.f; s0[3]=0.f;
      s1[0]=0.f; s1[1]=0.f; s1[2]=0.f; s1[3]=0.f;
      #pragma unroll
      for (int ks = 0; ks < 8; ks++) {
        uint32_t bb[4];
        uint32_t a = Ks + (((nb + nsel)*8 + rl) << 8) + (((2*ks + hf) ^ rl) << 4);
        ldsm_x4(bb[0], bb[1], bb[2], bb[3], a);
        mma_bf16(s0, qa[ks], bb,     s0);
        mma_bf16(s1, qa[ks], bb + 2, s1);
      }
    }

    // ---- exp + row sums ----
    float rs0 = 0.f, rs1 = 0.f;
    #pragma unroll
    for (int nb = 0; nb < 8; nb++) {
      float p0 = __expf(fminf(sacc[nb][0]*SCALE, 80.f));
      float p1 = __expf(fminf(sacc[nb][1]*SCALE, 80.f));
      float p2 = __expf(fminf(sacc[nb][2]*SCALE, 80.f));
      float p3 = __expf(fminf(sacc[nb][3]*SCALE, 80.f));
      sacc[nb][0]=p0; sacc[nb][1]=p1; sacc[nb][2]=p2; sacc[nb][3]=p3;
      rs0 += p0 + p1;
      rs1 += p2 + p3;
    }
    rs0 += __shfl_xor_sync(0xffffffffu, rs0, 1);
    rs0 += __shfl_xor_sync(0xffffffffu, rs0, 2);
    rs1 += __shfl_xor_sync(0xffffffffu, rs1, 1);
    rs1 += __shfl_xor_sync(0xffffffffu, rs1, 2);
    l0 += rs0;
    l1 += rs1;

    // ---- O += P V (x4-batched trans B loads: two ch-blocks per ldsm) ----
    #pragma unroll
    for (int ks = 0; ks < 4; ks++) {
      uint32_t pa[4];
      pa[0] = pk2(sacc[2*ks][0],   sacc[2*ks][1]);
      pa[1] = pk2(sacc[2*ks][2],   sacc[2*ks][3]);
      pa[2] = pk2(sacc[2*ks+1][0], sacc[2*ks+1][1]);
      pa[3] = pk2(sacc[2*ks+1][2], sacc[2*ks+1][3]);
      int vrow = ks*16 + (lane & 15);
      uint32_t abase = Vs + vrow*256;
      uint32_t sw = (uint32_t)(vrow & 7) << 4;
      #pragma unroll
      for (int nb = 0; nb < 16; nb += 2) {
        uint32_t bb[4];
        uint32_t a = abase + (((uint32_t)((nb + nsel) << 4)) ^ sw);
        ldsm_x4_tr(bb[0], bb[1], bb[2], bb[3], a);
        mma_bf16(oacc[nb],   pa, bb,     oacc[nb]);
        mma_bf16(oacc[nb+1], pa, bb + 2, oacc[nb+1]);
      }
    }

    __syncthreads();
    if (kt + 2 < 32) {
      int kb = kb0 + ((kt + 2) << 6);
      uint32_t base = sb + (uint32_t)(kt & 1)*32768;
      for (int i = t; i < 1024; i += 256) {
        int row = i >> 4, cb = i & 15;
        uint32_t d = base + row*256 + ((cb ^ (row & 7)) << 4);
        cpa16(d,          Kg + ((size_t)(kb + row))*CC + cb*8);
        cpa16(d + 16384,  Vg + ((size_t)(kb + row))*CC + cb*8);
      }
      cp_commit();
    }
  }

  // ---- epilogue: bf16 partial O and fp32 l ----
  int r0 = q0 + w*16 + (lane >> 2);
  __nv_bfloat16* Og = g_Opb + ((size_t)(b*2 + sp)*NN + r0)*CC;
  int col = (lane & 3)*2;
  #pragma unroll
  for (int nb = 0; nb < 16; nb++) {
    *(uint32_t*)(Og + nb*8 + col)                = pk2(oacc[nb][0], oacc[nb][1]);
    *(uint32_t*)(Og + (size_t)8*CC + nb*8 + col) = pk2(oacc[nb][2], oacc[nb][3]);
  }
  if ((lane & 3) == 0) {
    g_l[(size_t)(b*2 + sp)*NN + r0]     = l0;
    g_l[(size_t)(b*2 + sp)*NN + r0 + 8] = l1;
  }
}

// ---------------------------------------------------------------------------
// Kernel 3b: combine bf16 split-KV partials -> g_Ab [b][n][c] bf16
// ---------------------------------------------------------------------------
__global__ __launch_bounds__(256) void combine_kernel() {
  int gi  = blockIdx.x * 256 + threadIdx.x;   // uint4 index (8 bf16) over [B][N][C]
  int ngl = gi >> 4;                          // b*NN + n
  int b   = ngl >> 12;
  int n   = ngl & 4095;
  float l = g_l[(size_t)(b*2)*NN + n] + g_l[(size_t)(b*2+1)*NN + n];
  float inv = 1.f / l;
  const uint4* O = (const uint4*)g_Opb;
  uint4 ua = O[gi + (size_t)b*65536];
  uint4 uc = O[gi + (size_t)b*65536 + 65536];
  const __nv_bfloat162* pa = (const __nv_bfloat162*)&ua;
  const __nv_bfloat162* pc = (const __nv_bfloat162*)&uc;
  uint4 o;
  uint32_t* po = (uint32_t*)&o;
  #pragma unroll
  for (int j = 0; j < 4; j++) {
    float2 fa = __bfloat1622float2(pa[j]);
    float2 fc = __bfloat1622float2(pc[j]);
    po[j] = pk2((fa.x + fc.x)*inv, (fa.y + fc.y)*inv);
  }
  ((uint4*)g_Ab)[gi] = o;
}

// ---------------------------------------------------------------------------
// Kernel 4: projection + bias + residual, HMMA, x4-batched.
// ---------------------------------------------------------------------------
__global__ __launch_bounds__(256) void proj_kernel(
    const float* __restrict__ x,
    const float* __restrict__ wp,
    const float* __restrict__ bp,
    float* __restrict__ outp) {
  char* smem = dynsmem;
  uint32_t sb = smem_u32(smem);
  uint32_t sbW = sb + 32768;
  float* Ot = (float*)smem;

  int b  = blockIdx.x >> 5;
  int n0 = (blockIdx.x & 31) << 7;
  int t  = threadIdx.x;
  int w  = t >> 5;
  int lane = t & 31;

  for (int i = t; i < 2048; i += 256) {
    int row = i >> 4, cb = i & 15;
    *(uint4*)(smem + row*256 + ((cb ^ (row & 7)) << 4)) =
        *(const uint4*)(g_Ab + ((size_t)b*NN + n0 + row)*CC + cb*8);
  }
  for (int i = t; i < 2048; i += 256) {
    int co = i >> 4, j8 = i & 15;
    const float4* pw = (const float4*)(wp + co*CC + j8*8);
    float4 f0 = pw[0], f1 = pw[1];
    uint4 o;
    o.x = pk2(f0.x, f0.y); o.y = pk2(f0.z, f0.w);
    o.z = pk2(f1.x, f1.y); o.w = pk2(f1.z, f1.w);
    *(uint4*)(smem + 32768 + co*256 + ((j8 ^ (co & 7)) << 4)) = o;
  }
  __syncthreads();

  uint32_t qa[8][4];
  {
    int row = w*16 + (lane & 15);
    int kc  = (lane >> 4) & 1;
    #pragma unroll
    for (int ks = 0; ks < 8; ks++) {
      uint32_t a = sb + row*256 + (((2*ks + kc) ^ (row & 7)) << 4);
      ldsm_x4(qa[ks][0], qa[ks][1], qa[ks][2], qa[ks][3], a);
    }
  }

  int rl   = lane & 7;
  int hf   = (lane >> 3) & 1;
  int nsel = (lane >> 4) & 1;

  float acc[16][4];
  #pragma unroll
  for (int nb = 0; nb < 16; nb += 2) {
    float* a0 = acc[nb];
    float* a1 = acc[nb+1];
    a0[0]=0.f; a0[1]=0.f; a0[2]=0.f; a0[3]=0.f;
    a1[0]=0.f; a1[1]=0.f; a1[2]=0.f; a1[3]=0.f;
    #pragma unroll
    for (int ks = 0; ks < 8; ks++) {
      uint32_t bb[4];
      uint32_t a = sbW + ((nb + nsel)*8 + rl)*256 + (((2*ks + hf) ^ rl) << 4);
      ldsm_x4(bb[0], bb[1], bb[2], bb[3], a);
      mma_bf16(a0, qa[ks], bb,     a0);
      mma_bf16(a1, qa[ks], bb + 2, a1);
    }
  }
  __syncthreads();   // reuse smem as Ot[128co][132]

  int nl = w*16 + (lane >> 2);
  #pragma unroll
  for (int nb = 0; nb < 16; nb++) {
    int co0 = nb*8 + (lane & 3)*2;
    Ot[co0*132 + nl]           = acc[nb][0];
    Ot[(co0 + 1)*132 + nl]     = acc[nb][1];
    Ot[co0*132 + nl + 8]       = acc[nb][2];
    Ot[(co0 + 1)*132 + nl + 8] = acc[nb][3];
  }
  __syncthreads();

  for (int i = t; i < 4096; i += 256) {
    int co = i >> 5, q = i & 31;
    float bias = bp[co];
    size_t base = (size_t)b*CC*NN + (size_t)co*NN + n0 + q*4;
    float4 xv = *(const float4*)&x[base];
    float4 hv = *(float4*)&Ot[co*132 + q*4];
    float4 o;
    o.x = xv.x + hv.x + bias;
    o.y = xv.y + hv.y + bias;
    o.z = xv.z + hv.z + bias;
    o.w = xv.w + hv.w + bias;
    *(float4*)&outp[base] = o;
  }
}

// ---------------------------------------------------------------------------
extern "C" void kernel_launch(void* const* d_in, const int* in_sizes, int n_in,
                              void* d_out, int out_size) {
  (void)in_sizes; (void)n_in; (void)out_size;
  const float* x    = (const float*)d_in[0];
  const float* gn_w = (const float*)d_in[1];
  const float* gn_b = (const float*)d_in[2];
  const float* wq   = (const float*)d_in[3];
  const float* bq   = (const float*)d_in[4];
  const float* wk   = (const float*)d_in[5];
  const float* bk   = (const float*)d_in[6];
  const float* wv   = (const float*)d_in[7];
  const float* bv   = (const float*)d_in[8];
  const float* wp   = (const float*)d_in[9];
  const float* bp   = (const float*)d_in[10];
  float* out = (float*)d_out;

  const int QKV_SMEM  = 65536;
  const int ATTN_SMEM = 65536;
  const int PROJ_SMEM = 128*132*4;   // 67584
  cudaFuncSetAttribute(qkv_kernel,  cudaFuncAttributeMaxDynamicSharedMemorySize, QKV_SMEM);
  cudaFuncSetAttribute(attn_kernel, cudaFuncAttributeMaxDynamicSharedMemorySize, ATTN_SMEM);
  cudaFuncSetAttribute(proj_kernel, cudaFuncAttributeMaxDynamicSharedMemorySize, PROJ_SMEM);

  gn_stats_kernel<<<64, 256>>>(x);
  qkv_kernel<<<64, 256, QKV_SMEM>>>(x, gn_w, gn_b, wq, bq, wk, bk, wv, bv);
  attn_kernel<<<128, 256, ATTN_SMEM>>>();
  combine_kernel<<<512, 256>>>();
  proj_kernel<<<64, 256, PROJ_SMEM>>>(x, wp, bp, out);
}